// round 13
// baseline (speedup 1.0000x reference)
#include <cuda_runtime.h>
#include <cuda_fp16.h>
#include <cstdint>

#define N_NODES 100000
#define N_ROWS_PAD 100096              // 1564 * 64
#define N_EDGES 1600000
#define HID     128
#define IN_DIM  16
#define LN_EPS  1e-5f
#define SCAN_B  512
#define LO_SCALE 2048.0f
#define LO_INV   (1.0f / 2048.0f)

typedef unsigned long long ull;

// ---------------- device scratch ----------------
__device__ int    g_deg[N_NODES];
__device__ float  g_dis[N_NODES];
__device__ int    g_off[N_NODES];
__device__ int    g_end[N_NODES];
__device__ int2   g_csr[N_EDGES];
__device__ float  g_h[(size_t)N_NODES * HID];      // f32 features (residual source)
__device__ __half g_hh[(size_t)N_NODES * HID];     // fp16 features (gather operand)
__device__ __half g_ph[(size_t)N_ROWS_PAD * HID];  // fp16 aggregated (GEMM A), padded zeros
__device__ ull    g_wsplit[3 * 64 * HID];          // pre-split W: (hi-pair | lo-pair<<32)
__device__ int    g_total;
__device__ int    g_wide;

// ---------------- fp16 helpers ----------------
__device__ __forceinline__ void split_fp16(float x, uint16_t& hi, uint16_t& lo) {
    __half h = __float2half_rn(x);
    float r = (x - __half2float(h)) * LO_SCALE;   // scaled into fp16 normal range
    __half l = __float2half_rn(r);
    hi = __half_as_ushort(h);
    lo = __half_as_ushort(l);
}
__device__ __forceinline__ void mma_fp16(float c[4], const uint32_t a[4],
                                         uint32_t b0, uint32_t b1) {
    asm("mma.sync.aligned.m16n8k16.row.col.f32.f16.f16.f32 "
        "{%0,%1,%2,%3}, {%4,%5,%6,%7}, {%8,%9}, {%0,%1,%2,%3};"
        : "+f"(c[0]), "+f"(c[1]), "+f"(c[2]), "+f"(c[3])
        : "r"(a[0]), "r"(a[1]), "r"(a[2]), "r"(a[3]), "r"(b0), "r"(b1));
}

// ---------------- pre-split all 3 layers' W (once per launch) ----------------
__global__ void k_prep_w(const float* __restrict__ Wc) {
    int i = blockIdx.x * blockDim.x + threadIdx.x;   // over 3*64*128
    if (i >= 3 * 64 * HID) return;
    int l = i / (64 * HID);
    int r = i - l * 64 * HID;
    int kp = r >> 7, n = r & 127;
    const float* W = Wc + (size_t)l * HID * HID;
    uint16_t h0, l0, h1, l1;
    split_fp16(W[(2 * kp) * HID + n], h0, l0);
    split_fp16(W[(2 * kp + 1) * HID + n], h1, l1);
    uint32_t hp = (uint32_t)h0 | ((uint32_t)h1 << 16);
    uint32_t lp = (uint32_t)l0 | ((uint32_t)l1 << 16);
    g_wsplit[i] = (ull)hp | ((ull)lp << 32);
}

// ---------------- zero + edge dtype detection (merged) ----------------
__global__ void k_zero_detect(const unsigned int* __restrict__ e32, int nwords) {
    int i = blockIdx.x * blockDim.x + threadIdx.x;
    if (i < N_NODES) g_deg[i] = 0;
    if (i == 0) g_total = 0;
    if (blockIdx.x == 0) {
        __shared__ unsigned int s_or;
        if (threadIdx.x == 0) s_or = 0u;
        __syncthreads();
        unsigned int v = 0u;
        for (int j = threadIdx.x * 2 + 1; j < nwords; j += blockDim.x * 2) v |= e32[j];
        atomicOr(&s_or, v);
        __syncthreads();
        if (threadIdx.x == 0) g_wide = (s_or == 0u) ? 1 : 0;
    }
}

__device__ __forceinline__ int load_edge(const void* eidx, long idx, int wide) {
    if (wide) return (int)((const long long*)eidx)[idx];
    return ((const int*)eidx)[idx];
}

// ---------------- CSR build ----------------
__global__ void k_hist(const void* __restrict__ eidx, int E) {
    int i = blockIdx.x * blockDim.x + threadIdx.x;
    if (i >= E) return;
    atomicAdd(&g_deg[load_edge(eidx, (long)E + i, g_wide)], 1);
}

__global__ void k_alloc() {
    __shared__ int s[SCAN_B];
    __shared__ int sbase;
    int tid = threadIdx.x;
    int i = blockIdx.x * SCAN_B + tid;
    int v = (i < N_NODES) ? g_deg[i] : 0;
    s[tid] = v;
    __syncthreads();
    for (int o = 1; o < SCAN_B; o <<= 1) {
        int t = (tid >= o) ? s[tid - o] : 0;
        __syncthreads();
        s[tid] += t;
        __syncthreads();
    }
    if (tid == SCAN_B - 1) sbase = atomicAdd(&g_total, s[SCAN_B - 1]);
    __syncthreads();
    int off = sbase + s[tid] - v;
    if (i < N_NODES) {
        g_off[i] = off;
        g_end[i] = off + v;
        g_dis[i] = rsqrtf((float)(v + 1));
        g_deg[i] = off;
    }
}

__global__ void k_fill(const void* __restrict__ eidx, int E) {
    int i = blockIdx.x * blockDim.x + threadIdx.x;
    if (i >= E) return;
    int wide = g_wide;
    int sidx = load_edge(eidx, i, wide);
    int didx = load_edge(eidx, (long)E + i, wide);
    int pos = atomicAdd(&g_deg[didx], 1);
    g_csr[pos] = make_int2(sidx, __float_as_int(g_dis[sidx]));
}

// ---------------- input projection (writes f32 + fp16 copies) ----------------
__global__ void k_proj(const float* __restrict__ x, const float* __restrict__ Win,
                       const float* __restrict__ bin) {
    __shared__ float sW[IN_DIM * HID];
    __shared__ float sx[8 * IN_DIM];
    int tid = threadIdx.x;
    for (int i = tid; i < IN_DIM * HID; i += 128) sW[i] = Win[i];
    int base = blockIdx.x * 8;
    {
        int n = tid / IN_DIM, k = tid % IN_DIM;
        int node = base + n;
        sx[tid] = (node < N_NODES) ? x[(size_t)node * IN_DIM + k] : 0.f;
    }
    __syncthreads();
    float bc = bin[tid];
    for (int n = 0; n < 8; n++) {
        int node = base + n;
        if (node >= N_NODES) break;
        float sum = bc;
#pragma unroll
        for (int k = 0; k < IN_DIM; k++) sum += sx[n * IN_DIM + k] * sW[k * HID + tid];
        g_h[(size_t)node * HID + tid] = sum;
        g_hh[(size_t)node * HID + tid] = __float2half(sum);
    }
}

// ---------------- propagate: fp16 operands, f32 accumulate, fp16 output ----------------
__device__ __forceinline__ void fma_h8(float4& acc, float w, uint2 raw) {
    float2 f01 = __half22float2(*reinterpret_cast<__half2*>(&raw.x));
    float2 f23 = __half22float2(*reinterpret_cast<__half2*>(&raw.y));
    acc.x += w * f01.x; acc.y += w * f01.y;
    acc.z += w * f23.x; acc.w += w * f23.y;
}

__global__ void k_gather() {
    int warp = threadIdx.x >> 5, lane = threadIdx.x & 31;
    int d = blockIdx.x * 8 + warp;
    if (d >= N_NODES) return;
    int start = g_off[d], end = g_end[d];
    float dd = g_dis[d];
    const uint2* hh = (const uint2*)g_hh;
    float4 acc = make_float4(0.f, 0.f, 0.f, 0.f);
    fma_h8(acc, dd, hh[(size_t)d * 32 + lane]);  // self term
    for (int j = start; j < end; j += 32) {
        int2 ew = make_int2(0, 0);
        if (j + lane < end) ew = g_csr[j + lane];
        int cnt = min(32, end - j);
        int t = 0;
        for (; t + 4 <= cnt; t += 4) {
            int s0 = __shfl_sync(0xffffffffu, ew.x, t);
            int s1 = __shfl_sync(0xffffffffu, ew.x, t + 1);
            int s2 = __shfl_sync(0xffffffffu, ew.x, t + 2);
            int s3 = __shfl_sync(0xffffffffu, ew.x, t + 3);
            float w0 = __int_as_float(__shfl_sync(0xffffffffu, ew.y, t));
            float w1 = __int_as_float(__shfl_sync(0xffffffffu, ew.y, t + 1));
            float w2 = __int_as_float(__shfl_sync(0xffffffffu, ew.y, t + 2));
            float w3 = __int_as_float(__shfl_sync(0xffffffffu, ew.y, t + 3));
            uint2 v0 = hh[(size_t)s0 * 32 + lane];
            uint2 v1 = hh[(size_t)s1 * 32 + lane];
            uint2 v2 = hh[(size_t)s2 * 32 + lane];
            uint2 v3 = hh[(size_t)s3 * 32 + lane];
            fma_h8(acc, w0, v0);
            fma_h8(acc, w1, v1);
            fma_h8(acc, w2, v2);
            fma_h8(acc, w3, v3);
        }
        for (; t < cnt; t++) {
            int   s = __shfl_sync(0xffffffffu, ew.x, t);
            float w = __int_as_float(__shfl_sync(0xffffffffu, ew.y, t));
            fma_h8(acc, w, hh[(size_t)s * 32 + lane]);
        }
    }
    acc.x *= dd; acc.y *= dd; acc.z *= dd; acc.w *= dd;
    __half2 o01 = __floats2half2_rn(acc.x, acc.y);
    __half2 o23 = __floats2half2_rn(acc.z, acc.w);
    uint2 st;
    st.x = *reinterpret_cast<uint32_t*>(&o01);
    st.y = *reinterpret_cast<uint32_t*>(&o23);
    ((uint2*)g_ph)[(size_t)d * 32 + lane] = st;
}

// ---------------- transform via mma.sync fp16 m16n8k16 ----------------
// A = fp16(p) unsplit; B = pre-split W loaded from g_wsplit (raw copy, no math).
// Block: 64-row tile, 256 threads = 8 warps (4 row-groups x 2 col-groups).
// smem (u32): sA [64][68] u32 (half2 pairs), sB [64][136] u64.
// Total: 17.4KB + 69.6KB = 87KB -> 2 blocks/SM.
#define ASTR 68
#define BSTR 136
#define SM_A 0
#define SM_B_U32 (64 * ASTR)
#define SM_U32_TOTAL (64 * ASTR + 64 * BSTR * 2)

__global__ void __launch_bounds__(256, 2) k_transform_fp(
        const ull* __restrict__ Wsp, const float* __restrict__ bias,
        const float* __restrict__ gamma, const float* __restrict__ beta,
        float* __restrict__ out, int add_res, int write_half) {
    extern __shared__ uint32_t smem[];
    __shared__ float sBias[HID], sG[HID], sBe[HID];
    __shared__ float psum[2][64], psq[2][64];
    int tid = threadIdx.x;
    int rbase = blockIdx.x * 64;

    for (int i = tid; i < HID; i += 256) {
        sBias[i] = bias[i];
        sG[i] = gamma[i];
        sBe[i] = beta[i];
    }
    // stage W: straight ulonglong2 copy of pre-split pairs (n even/odd contiguous)
    {
        ull* sB = (ull*)(smem + SM_B_U32);
        const ulonglong2* gw2 = (const ulonglong2*)Wsp;
        for (int i = tid; i < 64 * HID / 2; i += 256) {        // 4096 u128s
            int kp = i >> 6, n2 = i & 63;
            ulonglong2 v = gw2[i];
            *(ulonglong2*)(sB + kp * BSTR + n2 * 2) = v;
        }
    }
    // stage A: straight u32 copy of fp16 pairs
    {
        const uint32_t* ph = (const uint32_t*)g_ph;
        for (int i = tid; i < 64 * 64; i += 256) {
            int r = i >> 6, kp = i & 63;
            smem[SM_A + r * ASTR + kp] = ph[(size_t)(rbase + r) * 64 + kp];
        }
    }
    __syncthreads();

    int warp = tid >> 5, lane = tid & 31;
    int grp = lane >> 2, qid = lane & 3;
    int wr = warp >> 1, wc = warp & 1;
    int row0 = wr * 16;
    int col0 = wc * 64;

    float accH[8][4], accL[8][4];
#pragma unroll
    for (int n = 0; n < 8; n++)
#pragma unroll
        for (int c = 0; c < 4; c++) { accH[n][c] = 0.f; accL[n][c] = 0.f; }

    const uint32_t* sA = smem + SM_A;
    const ull* sB = (const ull*)(smem + SM_B_U32);

#pragma unroll 2
    for (int ks = 0; ks < 8; ks++) {
        int kb = 8 * ks;
        int raA = (row0 + grp) * ASTR + kb;
        int raB = raA + 8 * ASTR;
        uint32_t a[4];
        a[0] = sA[raA + qid];
        a[1] = sA[raB + qid];
        a[2] = sA[raA + qid + 4];
        a[3] = sA[raB + qid + 4];
#pragma unroll
        for (int n = 0; n < 8; n++) {
            ull bv0 = sB[(kb + qid) * BSTR + col0 + n * 8 + grp];
            ull bv1 = sB[(kb + qid + 4) * BSTR + col0 + n * 8 + grp];
            mma_fp16(accH[n], a, (uint32_t)bv0, (uint32_t)bv1);
            mma_fp16(accL[n], a, (uint32_t)(bv0 >> 32), (uint32_t)(bv1 >> 32));
        }
    }

    // recombine + bias + per-row partial sums
    float acc[8][4];
    float s[2] = {0.f, 0.f}, q[2] = {0.f, 0.f};
#pragma unroll
    for (int n = 0; n < 8; n++) {
        int c0 = col0 + n * 8 + 2 * qid;
        float b0 = sBias[c0], b1 = sBias[c0 + 1];
        acc[n][0] = accH[n][0] + accL[n][0] * LO_INV + b0;
        acc[n][1] = accH[n][1] + accL[n][1] * LO_INV + b1;
        acc[n][2] = accH[n][2] + accL[n][2] * LO_INV + b0;
        acc[n][3] = accH[n][3] + accL[n][3] * LO_INV + b1;
        s[0] += acc[n][0] + acc[n][1];
        q[0] += acc[n][0] * acc[n][0] + acc[n][1] * acc[n][1];
        s[1] += acc[n][2] + acc[n][3];
        q[1] += acc[n][2] * acc[n][2] + acc[n][3] * acc[n][3];
    }
#pragma unroll
    for (int o = 1; o <= 2; o <<= 1)
#pragma unroll
        for (int i = 0; i < 2; i++) {
            s[i] += __shfl_xor_sync(0xffffffffu, s[i], o);
            q[i] += __shfl_xor_sync(0xffffffffu, q[i], o);
        }
    if (qid == 0) {
#pragma unroll
        for (int i = 0; i < 2; i++) {
            int r = row0 + grp + i * 8;
            psum[wc][r] = s[i];
            psq[wc][r] = q[i];
        }
    }
    __syncthreads();

    float mu[2], rstd[2];
#pragma unroll
    for (int i = 0; i < 2; i++) {
        int r = row0 + grp + i * 8;
        float tot = psum[0][r] + psum[1][r];
        float tq  = psq[0][r] + psq[1][r];
        mu[i] = tot * (1.f / 128.f);
        rstd[i] = rsqrtf(fmaxf(tq * (1.f / 128.f) - mu[i] * mu[i], 0.f) + LN_EPS);
    }

    int ra = row0 + grp;
    int rb = ra + 8;
    int na = rbase + ra, nb2 = rbase + rb;
    __half2* hh2 = (__half2*)g_hh;
#pragma unroll
    for (int n = 0; n < 8; n++) {
        int c0 = col0 + n * 8 + 2 * qid;
        float g0 = sG[c0], g1 = sG[c0 + 1], e0 = sBe[c0], e1 = sBe[c0 + 1];
        if (na < N_NODES) {
            float2 o;
            o.x = fmaxf((acc[n][0] - mu[0]) * rstd[0] * g0 + e0, 0.f);
            o.y = fmaxf((acc[n][1] - mu[0]) * rstd[0] * g1 + e1, 0.f);
            if (add_res) {
                float2 hp = *(const float2*)(g_h + (size_t)na * HID + c0);
                o.x += hp.x; o.y += hp.y;
            }
            *(float2*)(out + (size_t)na * HID + c0) = o;
            if (write_half) hh2[(size_t)na * 64 + (c0 >> 1)] = __floats2half2_rn(o.x, o.y);
        }
        if (nb2 < N_NODES) {
            float2 o;
            o.x = fmaxf((acc[n][2] - mu[1]) * rstd[1] * g0 + e0, 0.f);
            o.y = fmaxf((acc[n][3] - mu[1]) * rstd[1] * g1 + e1, 0.f);
            if (add_res) {
                float2 hp = *(const float2*)(g_h + (size_t)nb2 * HID + c0);
                o.x += hp.x; o.y += hp.y;
            }
            *(float2*)(out + (size_t)nb2 * HID + c0) = o;
            if (write_half) hh2[(size_t)nb2 * 64 + (c0 >> 1)] = __floats2half2_rn(o.x, o.y);
        }
    }
}

// ---------------- launch ----------------
extern "C" void kernel_launch(void* const* d_in, const int* in_sizes, int n_in,
                              void* d_out, int out_size) {
    const float* x   = (const float*)d_in[0];
    const void*  eix = d_in[1];
    const float* Win = (const float*)d_in[2];
    const float* bin = (const float*)d_in[3];
    const float* Wc  = (const float*)d_in[4];
    const float* bc  = (const float*)d_in[5];
    const float* lg  = (const float*)d_in[6];
    const float* lb  = (const float*)d_in[7];
    int E = in_sizes[1] / 2;

    static bool attr_set = false;  // idempotent attribute set
    if (!attr_set) {
        cudaFuncSetAttribute(k_transform_fp, cudaFuncAttributeMaxDynamicSharedMemorySize,
                             SM_U32_TOTAL * (int)sizeof(uint32_t));
        attr_set = true;
    }

    void* h_addr = nullptr;
    cudaGetSymbolAddress(&h_addr, g_h);
    void* wsp_addr = nullptr;
    cudaGetSymbolAddress(&wsp_addr, g_wsplit);

    k_zero_detect<<<(N_NODES + 255) / 256, 256>>>((const unsigned int*)eix, 4096);
    k_prep_w<<<(3 * 64 * HID + 255) / 256, 256>>>(Wc);
    k_hist<<<(E + 255) / 256, 256>>>(eix, E);
    k_alloc<<<(N_NODES + SCAN_B - 1) / SCAN_B, SCAN_B>>>();
    k_fill<<<(E + 255) / 256, 256>>>(eix, E);

    k_proj<<<(N_NODES + 7) / 8, 128>>>(x, Win, bin);

    int tiles = N_ROWS_PAD / 64;  // 1564
    size_t tsmem = SM_U32_TOTAL * sizeof(uint32_t);  // ~87KB
    for (int l = 0; l < 3; l++) {
        k_gather<<<(N_NODES + 7) / 8, 256>>>();
        float* out = (l == 2) ? (float*)d_out : (float*)h_addr;
        k_transform_fp<<<tiles, 256, tsmem>>>(
            (const ull*)wsp_addr + (size_t)l * 64 * HID,
            bc + l * HID, lg + l * HID, lb + l * HID,
            out, (l > 0) ? 1 : 0, (l < 2) ? 1 : 0);
    }
}

// round 17
// speedup vs baseline: 1.2614x; 1.2614x over previous
#include <cuda_runtime.h>
#include <cuda_fp16.h>
#include <cstdint>

#define N_NODES 100000
#define N_ROWS_PAD 100096              // 1564 * 64
#define N_EDGES 1600000
#define HID     128
#define IN_DIM  16
#define LN_EPS  1e-5f
#define SCAN_B  512
#define LO_SCALE 2048.0f
#define LO_INV   (1.0f / 2048.0f)

typedef unsigned long long ull;

// ---------------- device scratch ----------------
__device__ int    g_deg[N_NODES];
__device__ float  g_dis[N_NODES];
__device__ int    g_off[N_NODES];
__device__ int    g_end[N_NODES];
__device__ int2   g_csr[N_EDGES];
__device__ __half g_hh[(size_t)N_NODES * HID];     // fp16 features (gather operand + residual)
__device__ __half g_ph[(size_t)N_ROWS_PAD * HID];  // fp16 aggregated (GEMM A), padded zeros
__device__ ull    g_wsplit[3 * 64 * HID];          // pre-split W: (hi-pair | lo-pair<<32)
__device__ int    g_total;
__device__ int    g_wide;

// ---------------- fp16 helpers ----------------
__device__ __forceinline__ void split_fp16(float x, uint16_t& hi, uint16_t& lo) {
    __half h = __float2half_rn(x);
    float r = (x - __half2float(h)) * LO_SCALE;
    __half l = __float2half_rn(r);
    hi = __half_as_ushort(h);
    lo = __half_as_ushort(l);
}
__device__ __forceinline__ void mma_fp16(float c[4], const uint32_t a[4],
                                         uint32_t b0, uint32_t b1) {
    asm("mma.sync.aligned.m16n8k16.row.col.f32.f16.f16.f32 "
        "{%0,%1,%2,%3}, {%4,%5,%6,%7}, {%8,%9}, {%0,%1,%2,%3};"
        : "+f"(c[0]), "+f"(c[1]), "+f"(c[2]), "+f"(c[3])
        : "r"(a[0]), "r"(a[1]), "r"(a[2]), "r"(a[3]), "r"(b0), "r"(b1));
}

// ---------------- pre: zero deg + detect dtype + pre-split W ----------------
__global__ void k_pre(const unsigned int* __restrict__ e32, int nwords,
                      const float* __restrict__ Wc) {
    int i = blockIdx.x * blockDim.x + threadIdx.x;
    if (i < N_NODES) g_deg[i] = 0;
    if (i == 0) g_total = 0;
    if (i < 3 * 64 * HID) {
        int l = i / (64 * HID);
        int r = i - l * 64 * HID;
        int kp = r >> 7, n = r & 127;
        const float* W = Wc + (size_t)l * HID * HID;
        uint16_t h0, l0, h1, l1;
        split_fp16(W[(2 * kp) * HID + n], h0, l0);
        split_fp16(W[(2 * kp + 1) * HID + n], h1, l1);
        uint32_t hp = (uint32_t)h0 | ((uint32_t)h1 << 16);
        uint32_t lp = (uint32_t)l0 | ((uint32_t)l1 << 16);
        g_wsplit[i] = (ull)hp | ((ull)lp << 32);
    }
    if (blockIdx.x == 0) {
        __shared__ unsigned int s_or;
        if (threadIdx.x == 0) s_or = 0u;
        __syncthreads();
        unsigned int v = 0u;
        for (int j = threadIdx.x * 2 + 1; j < nwords; j += blockDim.x * 2) v |= e32[j];
        atomicOr(&s_or, v);
        __syncthreads();
        if (threadIdx.x == 0) g_wide = (s_or == 0u) ? 1 : 0;
    }
}

__device__ __forceinline__ int load_edge(const void* eidx, long idx, int wide) {
    if (wide) return (int)((const long long*)eidx)[idx];
    return ((const int*)eidx)[idx];
}

// ---------------- CSR build ----------------
__global__ void k_hist(const void* __restrict__ eidx, int E) {
    int i = blockIdx.x * blockDim.x + threadIdx.x;
    if (i >= E) return;
    atomicAdd(&g_deg[load_edge(eidx, (long)E + i, g_wide)], 1);
}

__global__ void k_alloc() {
    __shared__ int s[SCAN_B];
    __shared__ int sbase;
    int tid = threadIdx.x;
    int i = blockIdx.x * SCAN_B + tid;
    int v = (i < N_NODES) ? g_deg[i] : 0;
    s[tid] = v;
    __syncthreads();
    for (int o = 1; o < SCAN_B; o <<= 1) {
        int t = (tid >= o) ? s[tid - o] : 0;
        __syncthreads();
        s[tid] += t;
        __syncthreads();
    }
    if (tid == SCAN_B - 1) sbase = atomicAdd(&g_total, s[SCAN_B - 1]);
    __syncthreads();
    int off = sbase + s[tid] - v;
    if (i < N_NODES) {
        g_off[i] = off;
        g_end[i] = off + v;
        g_dis[i] = rsqrtf((float)(v + 1));
        g_deg[i] = off;
    }
}

// ---------------- fused CSR fill + input projection ----------------
__global__ void k_fillproj(const void* __restrict__ eidx, int E, int fill_blocks,
                           const float* __restrict__ x, const float* __restrict__ Win,
                           const float* __restrict__ bin) {
    __shared__ float sW[IN_DIM * HID];
    __shared__ float sx[256];
    if ((int)blockIdx.x < fill_blocks) {
        int i = blockIdx.x * 256 + threadIdx.x;
        if (i >= E) return;
        int wide = g_wide;
        int sidx = load_edge(eidx, i, wide);
        int didx = load_edge(eidx, (long)E + i, wide);
        int pos = atomicAdd(&g_deg[didx], 1);
        g_csr[pos] = make_int2(sidx, __float_as_int(g_dis[sidx]));
    } else {
        int tid = threadIdx.x;
        for (int i = tid; i < IN_DIM * HID; i += 256) sW[i] = Win[i];
        int base = (blockIdx.x - fill_blocks) * 16;
        {
            int n = tid / IN_DIM, k = tid % IN_DIM;   // 16 nodes x 16 dims
            int node = base + n;
            sx[tid] = (node < N_NODES) ? x[(size_t)node * IN_DIM + k] : 0.f;
        }
        __syncthreads();
        int sub = tid >> 7, col = tid & 127;
        float bc = bin[col];
        for (int n = 0; n < 8; n++) {
            int nn = sub * 8 + n;
            int node = base + nn;
            if (node >= N_NODES) break;
            float sum = bc;
#pragma unroll
            for (int k = 0; k < IN_DIM; k++) sum += sx[nn * IN_DIM + k] * sW[k * HID + col];
            g_hh[(size_t)node * HID + col] = __float2half(sum);
        }
    }
}

// ---------------- propagate: 2 edges/warp, uint4 segments ----------------
__device__ __forceinline__ void fma_h8v(float* acc, float w, uint4 v) {
    float2 f;
    f = __half22float2(*reinterpret_cast<__half2*>(&v.x)); acc[0] += w * f.x; acc[1] += w * f.y;
    f = __half22float2(*reinterpret_cast<__half2*>(&v.y)); acc[2] += w * f.x; acc[3] += w * f.y;
    f = __half22float2(*reinterpret_cast<__half2*>(&v.z)); acc[4] += w * f.x; acc[5] += w * f.y;
    f = __half22float2(*reinterpret_cast<__half2*>(&v.w)); acc[6] += w * f.x; acc[7] += w * f.y;
}

__global__ void k_gather() {
    int warp = threadIdx.x >> 5, lane = threadIdx.x & 31;
    int d = blockIdx.x * 8 + warp;
    if (d >= N_NODES) return;
    int half = lane >> 4, hl = lane & 15;
    int start = g_off[d], end = g_end[d];
    float dd = g_dis[d];
    const uint4* hh4 = (const uint4*)g_hh;   // row = 16 x uint4 (8 halfs each)
    float acc[8] = {0.f, 0.f, 0.f, 0.f, 0.f, 0.f, 0.f, 0.f};
    if (half == 0) fma_h8v(acc, dd, hh4[(size_t)d * 16 + hl]);  // self term once
    for (int j = start; j < end; j += 32) {
        int2 ew = make_int2(0, 0);
        if (j + lane < end) ew = g_csr[j + lane];
        int cnt = min(32, end - j);
        for (int t = 0; t < cnt; t += 8) {
            int   s0 = __shfl_sync(0xffffffffu, ew.x, t + half);
            float w0 = __int_as_float(__shfl_sync(0xffffffffu, ew.y, t + half));
            int   s1 = __shfl_sync(0xffffffffu, ew.x, t + 2 + half);
            float w1 = __int_as_float(__shfl_sync(0xffffffffu, ew.y, t + 2 + half));
            int   s2 = __shfl_sync(0xffffffffu, ew.x, t + 4 + half);
            float w2 = __int_as_float(__shfl_sync(0xffffffffu, ew.y, t + 4 + half));
            int   s3 = __shfl_sync(0xffffffffu, ew.x, t + 6 + half);
            float w3 = __int_as_float(__shfl_sync(0xffffffffu, ew.y, t + 6 + half));
            uint4 v0 = hh4[(size_t)s0 * 16 + hl];
            uint4 v1 = hh4[(size_t)s1 * 16 + hl];
            uint4 v2 = hh4[(size_t)s2 * 16 + hl];
            uint4 v3 = hh4[(size_t)s3 * 16 + hl];
            fma_h8v(acc, w0, v0);
            fma_h8v(acc, w1, v1);
            fma_h8v(acc, w2, v2);
            fma_h8v(acc, w3, v3);
        }
    }
#pragma unroll
    for (int i = 0; i < 8; i++) {
        acc[i] += __shfl_xor_sync(0xffffffffu, acc[i], 16);
        acc[i] *= dd;
    }
    if (half == 0) {
        uint4 st;
        __half2 h01 = __floats2half2_rn(acc[0], acc[1]);
        __half2 h23 = __floats2half2_rn(acc[2], acc[3]);
        __half2 h45 = __floats2half2_rn(acc[4], acc[5]);
        __half2 h67 = __floats2half2_rn(acc[6], acc[7]);
        st.x = *reinterpret_cast<uint32_t*>(&h01);
        st.y = *reinterpret_cast<uint32_t*>(&h23);
        st.z = *reinterpret_cast<uint32_t*>(&h45);
        st.w = *reinterpret_cast<uint32_t*>(&h67);
        ((uint4*)g_ph)[(size_t)d * 16 + hl] = st;
    }
}

// ---------------- transform via mma.sync fp16 m16n8k16 ----------------
#define ASTR 68
#define BSTR 136
#define SM_A 0
#define SM_B_U32 (64 * ASTR)
#define SM_U32_TOTAL (64 * ASTR + 64 * BSTR * 2)

__global__ void __launch_bounds__(256, 2) k_transform_fp(
        const ull* __restrict__ Wsp, const float* __restrict__ bias,
        const float* __restrict__ gamma, const float* __restrict__ beta,
        float* __restrict__ out, int add_res, int write_f32) {
    extern __shared__ uint32_t smem[];
    __shared__ float sBias[HID], sG[HID], sBe[HID];
    __shared__ float psum[2][64], psq[2][64];
    int tid = threadIdx.x;
    int rbase = blockIdx.x * 64;

    for (int i = tid; i < HID; i += 256) {
        sBias[i] = bias[i];
        sG[i] = gamma[i];
        sBe[i] = beta[i];
    }
    {
        ull* sB = (ull*)(smem + SM_B_U32);
        const ulonglong2* gw2 = (const ulonglong2*)Wsp;
        for (int i = tid; i < 64 * HID / 2; i += 256) {
            int kp = i >> 6, n2 = i & 63;
            ulonglong2 v = gw2[i];
            *(ulonglong2*)(sB + kp * BSTR + n2 * 2) = v;
        }
    }
    {
        const uint32_t* ph = (const uint32_t*)g_ph;
        for (int i = tid; i < 64 * 64; i += 256) {
            int r = i >> 6, kp = i & 63;
            smem[SM_A + r * ASTR + kp] = ph[(size_t)(rbase + r) * 64 + kp];
        }
    }
    __syncthreads();

    int warp = tid >> 5, lane = tid & 31;
    int grp = lane >> 2, qid = lane & 3;
    int wr = warp >> 1, wc = warp & 1;
    int row0 = wr * 16;
    int col0 = wc * 64;

    float accH[8][4], accL[8][4];
#pragma unroll
    for (int n = 0; n < 8; n++)
#pragma unroll
        for (int c = 0; c < 4; c++) { accH[n][c] = 0.f; accL[n][c] = 0.f; }

    const uint32_t* sA = smem + SM_A;
    const ull* sB = (const ull*)(smem + SM_B_U32);

#pragma unroll 2
    for (int ks = 0; ks < 8; ks++) {
        int kb = 8 * ks;
        int raA = (row0 + grp) * ASTR + kb;
        int raB = raA + 8 * ASTR;
        uint32_t a[4];
        a[0] = sA[raA + qid];
        a[1] = sA[raB + qid];
        a[2] = sA[raA + qid + 4];
        a[3] = sA[raB + qid + 4];
#pragma unroll
        for (int n = 0; n < 8; n++) {
            ull bv0 = sB[(kb + qid) * BSTR + col0 + n * 8 + grp];
            ull bv1 = sB[(kb + qid + 4) * BSTR + col0 + n * 8 + grp];
            mma_fp16(accH[n], a, (uint32_t)bv0, (uint32_t)bv1);
            mma_fp16(accL[n], a, (uint32_t)(bv0 >> 32), (uint32_t)(bv1 >> 32));
        }
    }

    float acc[8][4];
    float s[2] = {0.f, 0.f}, q[2] = {0.f, 0.f};
#pragma unroll
    for (int n = 0; n < 8; n++) {
        int c0 = col0 + n * 8 + 2 * qid;
        float b0 = sBias[c0], b1 = sBias[c0 + 1];
        acc[n][0] = accH[n][0] + accL[n][0] * LO_INV + b0;
        acc[n][1] = accH[n][1] + accL[n][1] * LO_INV + b1;
        acc[n][2] = accH[n][2] + accL[n][2] * LO_INV + b0;
        acc[n][3] = accH[n][3] + accL[n][3] * LO_INV + b1;
        s[0] += acc[n][0] + acc[n][1];
        q[0] += acc[n][0] * acc[n][0] + acc[n][1] * acc[n][1];
        s[1] += acc[n][2] + acc[n][3];
        q[1] += acc[n][2] * acc[n][2] + acc[n][3] * acc[n][3];
    }
#pragma unroll
    for (int o = 1; o <= 2; o <<= 1)
#pragma unroll
        for (int i = 0; i < 2; i++) {
            s[i] += __shfl_xor_sync(0xffffffffu, s[i], o);
            q[i] += __shfl_xor_sync(0xffffffffu, q[i], o);
        }
    if (qid == 0) {
#pragma unroll
        for (int i = 0; i < 2; i++) {
            int r = row0 + grp + i * 8;
            psum[wc][r] = s[i];
            psq[wc][r] = q[i];
        }
    }
    __syncthreads();

    float mu[2], rstd[2];
#pragma unroll
    for (int i = 0; i < 2; i++) {
        int r = row0 + grp + i * 8;
        float tot = psum[0][r] + psum[1][r];
        float tq  = psq[0][r] + psq[1][r];
        mu[i] = tot * (1.f / 128.f);
        rstd[i] = rsqrtf(fmaxf(tq * (1.f / 128.f) - mu[i] * mu[i], 0.f) + LN_EPS);
    }

    int ra = row0 + grp;
    int rb = ra + 8;
    int na = rbase + ra, nb2 = rbase + rb;
    __half2* hh2 = (__half2*)g_hh;
#pragma unroll
    for (int n = 0; n < 8; n++) {
        int c0 = col0 + n * 8 + 2 * qid;
        float g0 = sG[c0], g1 = sG[c0 + 1], e0 = sBe[c0], e1 = sBe[c0 + 1];
        if (na < N_NODES) {
            float2 o;
            o.x = fmaxf((acc[n][0] - mu[0]) * rstd[0] * g0 + e0, 0.f);
            o.y = fmaxf((acc[n][1] - mu[0]) * rstd[0] * g1 + e1, 0.f);
            if (add_res) {
                float2 f = __half22float2(hh2[(size_t)na * 64 + (c0 >> 1)]);
                o.x += f.x; o.y += f.y;
            }
            if (write_f32) *(float2*)(out + (size_t)na * HID + c0) = o;
            else hh2[(size_t)na * 64 + (c0 >> 1)] = __floats2half2_rn(o.x, o.y);
        }
        if (nb2 < N_NODES) {
            float2 o;
            o.x = fmaxf((acc[n][2] - mu[1]) * rstd[1] * g0 + e0, 0.f);
            o.y = fmaxf((acc[n][3] - mu[1]) * rstd[1] * g1 + e1, 0.f);
            if (add_res) {
                float2 f = __half22float2(hh2[(size_t)nb2 * 64 + (c0 >> 1)]);
                o.x += f.x; o.y += f.y;
            }
            if (write_f32) *(float2*)(out + (size_t)nb2 * HID + c0) = o;
            else hh2[(size_t)nb2 * 64 + (c0 >> 1)] = __floats2half2_rn(o.x, o.y);
        }
    }
}

// ---------------- launch ----------------
extern "C" void kernel_launch(void* const* d_in, const int* in_sizes, int n_in,
                              void* d_out, int out_size) {
    const float* x   = (const float*)d_in[0];
    const void*  eix = d_in[1];
    const float* Win = (const float*)d_in[2];
    const float* bin = (const float*)d_in[3];
    const float* Wc  = (const float*)d_in[4];
    const float* bc  = (const float*)d_in[5];
    const float* lg  = (const float*)d_in[6];
    const float* lb  = (const float*)d_in[7];
    int E = in_sizes[1] / 2;

    static bool attr_set = false;  // idempotent attribute set
    if (!attr_set) {
        cudaFuncSetAttribute(k_transform_fp, cudaFuncAttributeMaxDynamicSharedMemorySize,
                             SM_U32_TOTAL * (int)sizeof(uint32_t));
        attr_set = true;
    }

    void* wsp_addr = nullptr;
    cudaGetSymbolAddress(&wsp_addr, g_wsplit);

    k_pre<<<(N_NODES + 255) / 256, 256>>>((const unsigned int*)eix, 4096, Wc);
    k_hist<<<(E + 255) / 256, 256>>>(eix, E);
    k_alloc<<<(N_NODES + SCAN_B - 1) / SCAN_B, SCAN_B>>>();
    int fb = (E + 255) / 256;
    int pb = (N_NODES + 15) / 16;  // 6250
    k_fillproj<<<fb + pb, 256>>>(eix, E, fb, x, Win, bin);

    int tiles = N_ROWS_PAD / 64;  // 1564
    size_t tsmem = SM_U32_TOTAL * sizeof(uint32_t);  // ~87KB
    for (int l = 0; l < 3; l++) {
        k_gather<<<(N_NODES + 7) / 8, 256>>>();
        k_transform_fp<<<tiles, 256, tsmem>>>(
            (const ull*)wsp_addr + (size_t)l * 64 * HID,
            bc + l * HID, lg + l * HID, lb + l * HID,
            (float*)d_out, (l > 0) ? 1 : 0, (l == 2) ? 1 : 0);
    }
}